// round 1
// baseline (speedup 1.0000x reference)
#include <cuda_runtime.h>
#include <math.h>

#define DD 32
#define HH 128
#define NB 128
#define NSTEPS 8

// G[j,k] = W2[j,k] * sum_i W3[i,j]*W1[k,i]  (x- and t-independent part of trace(J))
__device__ float g_G[HH * HH];

__constant__ float c_AC[6][5] = {
    {0.f, 0.f, 0.f, 0.f, 0.f},
    {0.2f, 0.f, 0.f, 0.f, 0.f},
    {3.f / 40.f, 9.f / 40.f, 0.f, 0.f, 0.f},
    {44.f / 45.f, -56.f / 15.f, 32.f / 9.f, 0.f, 0.f},
    {19372.f / 6561.f, -25360.f / 2187.f, 64448.f / 6561.f, -212.f / 729.f, 0.f},
    {9017.f / 3168.f, -355.f / 33.f, 46732.f / 5247.f, 49.f / 176.f, -5103.f / 18656.f}
};
__constant__ float c_CC[6] = {0.f, 0.2f, 0.3f, 0.8f, 8.f / 9.f, 1.f};
__constant__ float c_BW[6] = {35.f / 384.f, 0.f, 500.f / 1113.f, 125.f / 192.f,
                              -2187.f / 6784.f, 11.f / 84.f};

__global__ void precompute_G(const float* __restrict__ W1,
                             const float* __restrict__ W2,
                             const float* __restrict__ W3) {
    int j = blockIdx.x;   // 0..127
    int k = threadIdx.x;  // 0..127
    __shared__ float w3col[DD];
    if (k < DD) w3col[k] = W3[k * HH + j];
    __syncthreads();
    float c = 0.f;
#pragma unroll
    for (int i = 0; i < DD; i++) c = fmaf(w3col[i], W1[k * DD + i], c);
    g_G[j * HH + k] = W2[j * HH + k] * c;
}

__device__ __forceinline__ void fma2(unsigned long long& acc, unsigned long long a,
                                     unsigned long long b) {
    asm("fma.rn.f32x2 %0, %1, %2, %0;" : "+l"(acc) : "l"(a), "l"(b));
}
__device__ __forceinline__ unsigned long long add2(unsigned long long a,
                                                   unsigned long long b) {
    unsigned long long r;
    asm("add.rn.f32x2 %0, %1, %2;" : "=l"(r) : "l"(a), "l"(b));
    return r;
}
__device__ __forceinline__ float sum2(unsigned long long a) {
    float lo, hi;
    asm("mov.b64 {%0, %1}, %2;" : "=f"(lo), "=f"(hi) : "l"(a));
    return lo + hi;
}

__global__ __launch_bounds__(256, 1) void ode_kernel(
    const float* __restrict__ x0, const float* __restrict__ W1,
    const float* __restrict__ u1, const float* __restrict__ b1,
    const float* __restrict__ W2, const float* __restrict__ b2,
    const float* __restrict__ W3, const float* __restrict__ b3,
    const float* __restrict__ prec, float* __restrict__ out) {
    const float LOG2PI = 1.8378770664093453f;
    const float dt = 1.0f / NSTEPS;
    const int tid = threadIdx.x;
    const int b = blockIdx.x;

    __shared__ float W1s[HH * 33];   // padded rows (33) -> conflict-free row reads
    __shared__ float W3s[DD * 129];  // padded rows (129)
    __shared__ __align__(16) float h1s[HH];
    __shared__ __align__(16) float d1s[HH];
    __shared__ float h2s[HH];
    __shared__ float d2s[HH];
    __shared__ float u1s[HH], b1s[HH], b2s[HH];
    __shared__ float b3s[DD], precs[DD];
    __shared__ float ys[34], stx[34];
    __shared__ float ks[6][34];
    __shared__ float partial[128];
    __shared__ float tracep[4];
    __shared__ float s_logpx0;

    // --- stage small weights into smem ---
    for (int i = tid; i < HH * DD; i += 256) {
        int r = i >> 5, c = i & 31;
        W1s[r * 33 + c] = W1[i];
    }
    for (int i = tid; i < DD * HH; i += 256) {
        int r = i >> 7, c = i & 127;
        W3s[r * 129 + c] = W3[i];
    }
    if (tid < HH) {
        u1s[tid] = u1[tid];
        b1s[tid] = b1[tid];
        b2s[tid] = b2[tid];
    } else if (tid < HH + DD) {
        b3s[tid - HH] = b3[tid - HH];
        precs[tid - HH] = prec[tid - HH];
    }
    if (tid < 34) ys[tid] = (tid < DD) ? x0[b * DD + tid] : 0.f;

    // --- register-resident matrix row: W2 row (threads 0..127) or G row (128..255) ---
    unsigned long long wrow2[64];
    {
        const float* rp = (tid < HH) ? (W2 + tid * HH) : (g_G + (tid - HH) * HH);
        const ulonglong2* wp = (const ulonglong2*)rp;
#pragma unroll
        for (int m = 0; m < 32; m++) {
            ulonglong2 v = wp[m];
            wrow2[2 * m] = v.x;
            wrow2[2 * m + 1] = v.y;
        }
    }
    __syncthreads();

    // log p(x0) under N(0, I): sum(-0.5 x^2 - 0.5 log(2pi))
    if (tid < 32) {
        float xv = ys[tid];
        float v = fmaf(-0.5f * xv, xv, -0.5f * LOG2PI);
#pragma unroll
        for (int o = 16; o; o >>= 1) v += __shfl_xor_sync(0xffffffffu, v, o);
        if (tid == 0) s_logpx0 = v;
    }

    for (int step = 0; step < NSTEPS; step++) {
        float t0 = step * dt;
        for (int s = 0; s < 6; s++) {
            float ts = t0 + c_CC[s] * dt;

            // stage state: y + dt * sum_j a[s][j] * k_j
            if (tid < 34) {
                float v = ys[tid];
                for (int j = 0; j < s; j++) v = fmaf(dt * c_AC[s][j], ks[j][tid], v);
                stx[tid] = v;
            }
            __syncthreads();

            // h1 = tanh(W1 x + t u1 + b1), d1 = 1 - h1^2
            if (tid < HH) {
                float z = fmaf(ts, u1s[tid], b1s[tid]);
#pragma unroll
                for (int i = 0; i < DD; i++) z = fmaf(W1s[tid * 33 + i], stx[i], z);
                float h = tanhf(z);
                h1s[tid] = h;
                d1s[tid] = fmaf(-h, h, 1.f);
            }
            __syncthreads();

            // concurrent 128x128 matvecs: group A = W2 @ h1, group B = G @ d1
            float greg = 0.f;
            if (tid < HH) {
                unsigned long long a0 = 0ull, a1 = 0ull;
                const ulonglong2* v4 = (const ulonglong2*)h1s;
#pragma unroll
                for (int m = 0; m < 32; m++) {
                    ulonglong2 v = v4[m];
                    fma2(a0, wrow2[2 * m], v.x);
                    fma2(a1, wrow2[2 * m + 1], v.y);
                }
                float acc = sum2(add2(a0, a1)) + b2s[tid];
                float h2 = tanhf(acc);
                h2s[tid] = h2;
                d2s[tid] = fmaf(-h2, h2, 1.f);
            } else {
                unsigned long long a0 = 0ull, a1 = 0ull;
                const ulonglong2* v4 = (const ulonglong2*)d1s;
#pragma unroll
                for (int m = 0; m < 32; m++) {
                    ulonglong2 v = v4[m];
                    fma2(a0, wrow2[2 * m], v.x);
                    fma2(a1, wrow2[2 * m + 1], v.y);
                }
                greg = sum2(add2(a0, a1));
            }
            __syncthreads();

            // group A: dxdt partials (4 partial sums per output row);
            // group B: trace = sum_j d2[j] * (G d1)[j]
            if (tid < 128) {
                int i = tid & 31, part = tid >> 5;
                float p = 0.f;
                const int kb = part * 32;
#pragma unroll
                for (int kk = 0; kk < 32; kk++)
                    p = fmaf(W3s[i * 129 + kb + kk], h2s[kb + kk], p);
                partial[part * 32 + i] = p;
            } else {
                int j = tid - 128;
                float tv = d2s[j] * greg;
#pragma unroll
                for (int o = 16; o; o >>= 1) tv += __shfl_xor_sync(0xffffffffu, tv, o);
                if ((tid & 31) == 0) tracep[(tid >> 5) - 4] = tv;
            }
            __syncthreads();

            // assemble k_s: dxdt, dlogpdt, dkldt
            if (tid < 32) {
                float dx = partial[tid] + partial[32 + tid] + partial[64 + tid] +
                           partial[96 + tid] + b3s[tid];
                ks[s][tid] = dx;
                float xv = stx[tid];
                float r1 = fmaf(-0.5f * xv, xv, -0.5f * LOG2PI) * dx;  // log_p0 . dxdt
                float r2 = (-precs[tid] * xv) * dx;                    // gradlogpx . dxdt
#pragma unroll
                for (int o = 16; o; o >>= 1) {
                    r1 += __shfl_xor_sync(0xffffffffu, r1, o);
                    r2 += __shfl_xor_sync(0xffffffffu, r2, o);
                }
                if (tid == 0) {
                    float tr = tracep[0] + tracep[1] + tracep[2] + tracep[3];
                    float dlogp = -tr;
                    float omt = 1.f - ts;
                    float dkl = -0.5f * omt * omt * r1 - 0.5f * omt * (1.f + ts) * r2 +
                                omt * dlogp;
                    ks[s][32] = dlogp;
                    ks[s][33] = dkl;
                }
            }
            __syncthreads();
        }
        // y += dt * sum_s b[s] * k_s
        if (tid < 34) {
            float v = ys[tid];
#pragma unroll
            for (int s2 = 0; s2 < 6; s2++) v = fmaf(dt * c_BW[s2], ks[s2][tid], v);
            ys[tid] = v;
        }
        __syncthreads();
    }

    // outputs: z (B,D) | log_px0 + log_det (B,) | kl (B,)
    if (tid < DD) out[b * DD + tid] = ys[tid];
    else if (tid == DD) out[NB * DD + b] = s_logpx0 + ys[32];
    else if (tid == DD + 1) out[NB * DD + NB + b] = ys[33];
}

extern "C" void kernel_launch(void* const* d_in, const int* in_sizes, int n_in,
                              void* d_out, int out_size) {
    const float* x0 = (const float*)d_in[0];
    const float* W1 = (const float*)d_in[1];
    const float* u1 = (const float*)d_in[2];
    const float* b1 = (const float*)d_in[3];
    const float* W2 = (const float*)d_in[4];
    const float* b2 = (const float*)d_in[5];
    const float* W3 = (const float*)d_in[6];
    const float* b3 = (const float*)d_in[7];
    const float* prec = (const float*)d_in[8];
    float* out = (float*)d_out;

    precompute_G<<<HH, HH>>>(W1, W2, W3);
    ode_kernel<<<NB, 256>>>(x0, W1, u1, b1, W2, b2, W3, b3, prec, out);
}

// round 2
// speedup vs baseline: 1.1006x; 1.1006x over previous
#include <cuda_runtime.h>

#define DD 32
#define HH 128
#define NB 128
#define NSTEPS 8
#define LOG2PIF 1.8378770664093453f

__device__ __align__(16) float g_G[HH * HH];

typedef unsigned long long ull;

__global__ void precompute_G(const float* __restrict__ W1,
                             const float* __restrict__ W2,
                             const float* __restrict__ W3) {
    int j = blockIdx.x;   // 0..127
    int k = threadIdx.x;  // 0..127
    __shared__ float w3col[DD];
    if (k < DD) w3col[k] = W3[k * HH + j];
    __syncthreads();
    float c = 0.f;
#pragma unroll
    for (int i = 0; i < DD; i++) c = fmaf(w3col[i], W1[k * DD + i], c);
    g_G[j * HH + k] = W2[j * HH + k] * c;
}

__device__ __forceinline__ void fma2(ull& acc, ull a, ull b) {
    asm("fma.rn.f32x2 %0, %1, %2, %0;" : "+l"(acc) : "l"(a), "l"(b));
}
__device__ __forceinline__ ull add2(ull a, ull b) {
    ull r;
    asm("add.rn.f32x2 %0, %1, %2;" : "=l"(r) : "l"(a), "l"(b));
    return r;
}
__device__ __forceinline__ float sum2(ull a) {
    float lo, hi;
    asm("mov.b64 {%0, %1}, %2;" : "=f"(lo), "=f"(hi) : "l"(a));
    return lo + hi;
}
// tanh(x) = 1 - 2/(exp(2x)+1), via ex2.approx + rcp.approx (branch-free).
// Handles saturation naturally: e->inf => 1, e->0 => -1.
__device__ __forceinline__ float fast_tanh(float x) {
    float e, r;
    asm("ex2.approx.f32 %0, %1;" : "=f"(e) : "f"(x * 2.8853900817779268f));
    asm("rcp.approx.f32 %0, %1;" : "=f"(r) : "f"(e + 1.0f));
    return fmaf(-2.0f, r, 1.0f);
}

// Scalar finish for one stage: reduce partial arrays, accumulate y32/y33.
__device__ __forceinline__ void finish_stage(int lane, float tsp, float bws,
                                             const float* r1p, const float* r2p,
                                             const float* trp, float& y32,
                                             float& y33) {
    float v = 0.f;
    if (lane < 8) v = r1p[lane];
    else if (lane < 16) v = r2p[lane - 8];
    else if (lane < 20) v = trp[lane - 16];
    v += __shfl_xor_sync(0xffffffffu, v, 1);
    v += __shfl_xor_sync(0xffffffffu, v, 2);
    v += __shfl_xor_sync(0xffffffffu, v, 4);
    float R1 = __shfl_sync(0xffffffffu, v, 0);
    float R2 = __shfl_sync(0xffffffffu, v, 8);
    float TR = __shfl_sync(0xffffffffu, v, 16);
    float omt = 1.0f - tsp;
    float dlogp = -TR;
    float dkl =
        fmaf(-0.5f * omt * omt, R1, fmaf(-0.5f * omt * (1.0f + tsp), R2, omt * dlogp));
    y32 = fmaf(bws, dlogp, y32);
    y33 = fmaf(bws, dkl, y33);
}

__global__ __launch_bounds__(256, 1) void ode_kernel(
    const float* __restrict__ x0, const float* __restrict__ W1,
    const float* __restrict__ u1, const float* __restrict__ b1,
    const float* __restrict__ W2, const float* __restrict__ b2,
    const float* __restrict__ W3, const float* __restrict__ b3,
    const float* __restrict__ prec, float* __restrict__ out) {
    const int tid = threadIdx.x;
    const int lane = tid & 31;
    const int wid = tid >> 5;
    const int b = blockIdx.x;
    const float dtf = 1.0f / NSTEPS;

    const float CCc[6] = {0.f, 0.2f, 0.3f, 0.8f, 8.f / 9.f, 1.f};
    const float BWc[6] = {35.f / 384.f, 0.f, 500.f / 1113.f, 125.f / 192.f,
                          -2187.f / 6784.f, 11.f / 84.f};
    const float ACc[6][5] = {
        {0.f, 0.f, 0.f, 0.f, 0.f},
        {0.2f, 0.f, 0.f, 0.f, 0.f},
        {3.f / 40.f, 9.f / 40.f, 0.f, 0.f, 0.f},
        {44.f / 45.f, -56.f / 15.f, 32.f / 9.f, 0.f, 0.f},
        {19372.f / 6561.f, -25360.f / 2187.f, 64448.f / 6561.f, -212.f / 729.f, 0.f},
        {9017.f / 3168.f, -355.f / 33.f, 46732.f / 5247.f, 49.f / 176.f,
         -5103.f / 18656.f}};

    __shared__ __align__(16) float stxs[4][DD];  // per-warp stage-x (warps 0-3)
    __shared__ __align__(16) float h1s[HH];
    __shared__ __align__(16) float d1s[HH];
    __shared__ __align__(16) float h2s[HH];
    __shared__ float d2s[HH];
    __shared__ float ksx[6][DD];  // x-part of the 6 RK stage derivatives
    __shared__ float r1p[8], r2p[8], trp[4];
    __shared__ float s_logpx0;

    // ---- register-resident state & weights ----
    float yv = x0[b * DD + lane];  // lane i holds y_i (all warps redundantly)

    ull wr[64];  // full W2 row (tid<128) or G row (tid>=128): 128 floats
    {
        const float* rp = (tid < HH) ? (W2 + tid * HH) : (g_G + (tid - HH) * HH);
        const ulonglong2* wp = (const ulonglong2*)rp;
#pragma unroll
        for (int m = 0; m < 32; m++) {
            ulonglong2 v = wp[m];
            wr[2 * m] = v.x;
            wr[2 * m + 1] = v.y;
        }
    }
    ull w1r[16];  // W1 row (tid<128): 32 floats
    float u1r = 0.f, b1r = 0.f, b2r = 0.f;
    if (tid < HH) {
        const ulonglong2* wp = (const ulonglong2*)(W1 + tid * DD);
#pragma unroll
        for (int m = 0; m < 8; m++) {
            ulonglong2 v = wp[m];
            w1r[2 * m] = v.x;
            w1r[2 * m + 1] = v.y;
        }
        u1r = u1[tid];
        b1r = b1[tid];
        b2r = b2[tid];
    }
    const int i3 = tid >> 3, p3 = tid & 7;  // W3 row / 16-col slice
    ull w3r[8];
    {
        const ulonglong2* wp = (const ulonglong2*)(W3 + i3 * HH + p3 * 16);
#pragma unroll
        for (int m = 0; m < 4; m++) {
            ulonglong2 v = wp[m];
            w3r[2 * m] = v.x;
            w3r[2 * m + 1] = v.y;
        }
    }
    const float b3r = b3[i3];
    const float precr = prec[i3];
    float y32 = 0.f, y33 = 0.f;  // logdet / kl integrators (warp 4 owns)

    // log p(x0) under N(0,I)
    if (wid == 0) {
        float v = fmaf(-0.5f * yv, yv, -0.5f * LOG2PIF);
#pragma unroll
        for (int o = 16; o; o >>= 1) v += __shfl_xor_sync(0xffffffffu, v, o);
        if (lane == 0) s_logpx0 = v;
    }
    __syncthreads();

    for (int step = 0; step < NSTEPS; step++) {
        const float t0 = step * dtf;
        // y update from previous step's k's (all warps, registers)
        if (step > 0) {
            float acc = yv;
#pragma unroll
            for (int s = 0; s < 6; s++) acc = fmaf(dtf * BWc[s], ksx[s][lane], acc);
            yv = acc;
        }
#pragma unroll
        for (int s = 0; s < 6; s++) {
            const float ts = t0 + CCc[s] * dtf;

            // ---- P0/P1: stage-x in regs; warp4 finishes prev stage scalars; L1 ----
            float sx = yv;
#pragma unroll
            for (int j = 0; j < 5; j++)
                if (j < s) sx = fmaf(dtf * ACc[s][j], ksx[j][lane], sx);

            if (wid == 4 && !(step == 0 && s == 0)) {
                const float tsp = (s == 0) ? t0 : (t0 + CCc[s > 0 ? s - 1 : 0] * dtf);
                finish_stage(lane, tsp, dtf * BWc[(s + 5) % 6], r1p, r2p, trp, y32, y33);
            }
            if (wid < 4) {
                stxs[wid][lane] = sx;
                __syncwarp();
                ull a0 = 0ull, a1 = 0ull, a2 = 0ull, a3 = 0ull;
                const ulonglong2* xp = (const ulonglong2*)stxs[wid];
#pragma unroll
                for (int m = 0; m < 8; m++) {
                    ulonglong2 v = xp[m];
                    if (m & 1) {
                        fma2(a2, w1r[2 * m], v.x);
                        fma2(a3, w1r[2 * m + 1], v.y);
                    } else {
                        fma2(a0, w1r[2 * m], v.x);
                        fma2(a1, w1r[2 * m + 1], v.y);
                    }
                }
                float z = sum2(add2(add2(a0, a1), add2(a2, a3))) + fmaf(ts, u1r, b1r);
                float h = fast_tanh(z);
                h1s[tid] = h;
                d1s[tid] = fmaf(-h, h, 1.f);
            }
            __syncthreads();  // bar1

            // ---- P2: W2@h1 (tid<128) and G@d1 (tid>=128), register rows ----
            float greg = 0.f;
            {
                const ulonglong2* vp = (const ulonglong2*)((tid < HH) ? h1s : d1s);
                ull a0 = 0ull, a1 = 0ull, a2 = 0ull, a3 = 0ull;
#pragma unroll
                for (int m = 0; m < 32; m++) {
                    ulonglong2 v = vp[m];
                    if (m & 1) {
                        fma2(a2, wr[2 * m], v.x);
                        fma2(a3, wr[2 * m + 1], v.y);
                    } else {
                        fma2(a0, wr[2 * m], v.x);
                        fma2(a1, wr[2 * m + 1], v.y);
                    }
                }
                float acc = sum2(add2(add2(a0, a1), add2(a2, a3)));
                if (tid < HH) {
                    float h2 = fast_tanh(acc + b2r);
                    h2s[tid] = h2;
                    d2s[tid] = fmaf(-h2, h2, 1.f);
                } else {
                    greg = acc;
                }
            }
            __syncthreads();  // bar2

            // ---- P3: W3@h2 (all 256, 8 threads/row) + trace + r1/r2 partials ----
            {
                ull a0 = 0ull, a1 = 0ull;
                const ulonglong2* hp = (const ulonglong2*)(h2s + p3 * 16);
#pragma unroll
                for (int m = 0; m < 4; m++) {
                    ulonglong2 v = hp[m];
                    fma2(a0, w3r[2 * m], v.x);
                    fma2(a1, w3r[2 * m + 1], v.y);
                }
                float acc = sum2(add2(a0, a1));
                acc += __shfl_xor_sync(0xffffffffu, acc, 1);
                acc += __shfl_xor_sync(0xffffffffu, acc, 2);
                acc += __shfl_xor_sync(0xffffffffu, acc, 4);
                float dx = acc + b3r;  // all 8 lanes of the group have dx
                if ((lane & 7) == 0) ksx[s][i3] = dx;
                float xv = __shfl_sync(0xffffffffu, sx, i3 & 31);
                float w0 = fmaf(-0.5f * xv, xv, -0.5f * LOG2PIF);
                float r1c = w0 * dx;
                float r2c = -precr * xv * dx;
                r1c += __shfl_xor_sync(0xffffffffu, r1c, 8);
                r1c += __shfl_xor_sync(0xffffffffu, r1c, 16);
                r2c += __shfl_xor_sync(0xffffffffu, r2c, 8);
                r2c += __shfl_xor_sync(0xffffffffu, r2c, 16);
                if (lane == 0) {
                    r1p[wid] = r1c;
                    r2p[wid] = r2c;
                }
                if (tid >= HH) {
                    float tv = d2s[tid - HH] * greg;
#pragma unroll
                    for (int o = 16; o; o >>= 1)
                        tv += __shfl_xor_sync(0xffffffffu, tv, o);
                    if (lane == 0) trp[wid - 4] = tv;
                }
            }
            __syncthreads();  // bar3
        }
    }

    // final scalar finish (global stage 47, ts = 1.0)
    if (wid == 4) finish_stage(lane, 1.0f, dtf * BWc[5], r1p, r2p, trp, y32, y33);

    // outputs: z (B,D) | log_px0 + log_det (B,) | kl (B,)
    if (wid == 0) {
        float acc = yv;
#pragma unroll
        for (int s = 0; s < 6; s++) acc = fmaf(dtf * BWc[s], ksx[s][lane], acc);
        out[b * DD + lane] = acc;
    }
    if (wid == 4 && lane == 0) {
        out[NB * DD + b] = s_logpx0 + y32;
        out[NB * DD + NB + b] = y33;
    }
}

extern "C" void kernel_launch(void* const* d_in, const int* in_sizes, int n_in,
                              void* d_out, int out_size) {
    const float* x0 = (const float*)d_in[0];
    const float* W1 = (const float*)d_in[1];
    const float* u1 = (const float*)d_in[2];
    const float* b1 = (const float*)d_in[3];
    const float* W2 = (const float*)d_in[4];
    const float* b2 = (const float*)d_in[5];
    const float* W3 = (const float*)d_in[6];
    const float* b3 = (const float*)d_in[7];
    const float* prec = (const float*)d_in[8];
    float* out = (float*)d_out;

    precompute_G<<<HH, HH>>>(W1, W2, W3);
    ode_kernel<<<NB, 256>>>(x0, W1, u1, b1, W2, b2, W3, b3, prec, out);
}

// round 3
// speedup vs baseline: 1.1318x; 1.0283x over previous
#include <cuda_runtime.h>

#define DD 32
#define HH 128
#define NB 128
#define NSTEPS 8
#define NSTG 48
#define LOG2PIF 1.8378770664093453f

__device__ __align__(16) float g_G[HH * HH];

typedef unsigned long long ull;

__constant__ float c_CC[6] = {0.f, 0.2f, 0.3f, 0.8f, 8.f / 9.f, 1.f};
__constant__ float c_BW[6] = {35.f / 384.f, 0.f, 500.f / 1113.f, 125.f / 192.f,
                              -2187.f / 6784.f, 11.f / 84.f};

__global__ void precompute_G(const float* __restrict__ W1,
                             const float* __restrict__ W2,
                             const float* __restrict__ W3) {
    int j = blockIdx.x;   // 0..127
    int k = threadIdx.x;  // 0..127
    __shared__ float w3col[DD];
    if (k < DD) w3col[k] = W3[k * HH + j];
    __syncthreads();
    float c = 0.f;
#pragma unroll
    for (int i = 0; i < DD; i++) c = fmaf(w3col[i], W1[k * DD + i], c);
    g_G[j * HH + k] = W2[j * HH + k] * c;
}

__device__ __forceinline__ void fma2(ull& acc, ull a, ull b) {
    asm("fma.rn.f32x2 %0, %1, %2, %0;" : "+l"(acc) : "l"(a), "l"(b));
}
__device__ __forceinline__ ull add2(ull a, ull b) {
    ull r;
    asm("add.rn.f32x2 %0, %1, %2;" : "=l"(r) : "l"(a), "l"(b));
    return r;
}
__device__ __forceinline__ float sum2(ull a) {
    float lo, hi;
    asm("mov.b64 {%0, %1}, %2;" : "=f"(lo), "=f"(hi) : "l"(a));
    return lo + hi;
}
// tanh(x) = 1 - 2/(exp(2x)+1) via ex2.approx + rcp.approx (branch-free)
__device__ __forceinline__ float fast_tanh(float x) {
    float e, r;
    asm("ex2.approx.f32 %0, %1;" : "=f"(e) : "f"(x * 2.8853900817779268f));
    asm("rcp.approx.f32 %0, %1;" : "=f"(r) : "f"(e + 1.0f));
    return fmaf(-2.0f, r, 1.0f);
}

// vpool layout (floats): h1_lo @0, h1_hi @68, d1_lo @136, d1_hi @204.
// hi-copy offsets chosen so (hi_byte - lo_byte) = 272 == 16 mod 128 -> even/odd
// lanes hit disjoint bank groups on every LDS.128 wavefront.
#define V_H1LO 0
#define V_H1HI 68
#define V_D1LO 136
#define V_D1HI 204

__global__ __launch_bounds__(512, 1) void ode_kernel(
    const float* __restrict__ x0, const float* __restrict__ W1,
    const float* __restrict__ u1, const float* __restrict__ b1,
    const float* __restrict__ W2, const float* __restrict__ b2,
    const float* __restrict__ W3, const float* __restrict__ b3,
    const float* __restrict__ prec, float* __restrict__ out) {
    const int tid = threadIdx.x;
    const int lane = tid & 31;
    const int wid = tid >> 5;
    const int b = blockIdx.x;
    const float dtf = 1.0f / NSTEPS;

    const float BWc[6] = {35.f / 384.f, 0.f, 500.f / 1113.f, 125.f / 192.f,
                          -2187.f / 6784.f, 11.f / 84.f};
    const float CCc[6] = {0.f, 0.2f, 0.3f, 0.8f, 8.f / 9.f, 1.f};
    const float ACc[6][5] = {
        {0.f, 0.f, 0.f, 0.f, 0.f},
        {0.2f, 0.f, 0.f, 0.f, 0.f},
        {3.f / 40.f, 9.f / 40.f, 0.f, 0.f, 0.f},
        {44.f / 45.f, -56.f / 15.f, 32.f / 9.f, 0.f, 0.f},
        {19372.f / 6561.f, -25360.f / 2187.f, 64448.f / 6561.f, -212.f / 729.f, 0.f},
        {9017.f / 3168.f, -355.f / 33.f, 46732.f / 5247.f, 49.f / 176.f,
         -5103.f / 18656.f}};

    __shared__ float xsave[NSTG][DD];    // x(t) per stage
    __shared__ float dxsave[NSTG][DD];   // dx/dt per stage (doubles as RK ks)
    __shared__ float trsave[NSTG][HH];   // d2[j]*(G d1)[j] per stage
    __shared__ __align__(128) float vpool[272];
    __shared__ float h2s[HH], d2s[HH];
    __shared__ __align__(16) float stxs[16][DD];
    __shared__ float scal[NSTG][2];
    __shared__ float precs_s[DD];
    __shared__ float s_logpx0;

    float yv = x0[b * DD + lane];  // every warp holds full y in its 32 lanes

    // ---- register-resident weights ----
    const int grpB = (tid >= 256);
    const int r2 = (tid & 255) >> 1;  // L2 row (0..127)
    const int half = tid & 1;         // which 64-float half of the row
    ull wr[32];
    {
        const float* rp =
            grpB ? (g_G + r2 * HH + half * 64) : (W2 + r2 * HH + half * 64);
        const ulonglong2* wp = (const ulonglong2*)rp;
#pragma unroll
        for (int m = 0; m < 16; m++) {
            ulonglong2 v = wp[m];
            wr[2 * m] = v.x;
            wr[2 * m + 1] = v.y;
        }
    }
    const int r1 = tid >> 2, p1 = tid & 3;  // W1: 4 threads/row, 8 floats each
    ull w1r[4];
    {
        const ulonglong2* wp = (const ulonglong2*)(W1 + r1 * DD + p1 * 8);
#pragma unroll
        for (int m = 0; m < 2; m++) {
            ulonglong2 v = wp[m];
            w1r[2 * m] = v.x;
            w1r[2 * m + 1] = v.y;
        }
    }
    float u1r = 0.f, b1r = 0.f;
    if (p1 == 0) { u1r = u1[r1]; b1r = b1[r1]; }
    float b2r = 0.f;
    if (!grpB && half == 0) b2r = b2[r2];
    const int r3 = tid >> 3, p3 = tid & 7;  // W3: 8 threads/row, 16 floats each
    ull w3r[8];
    float b3r = 0.f;
    if (tid < 256) {
        const ulonglong2* wp = (const ulonglong2*)(W3 + r3 * HH + p3 * 16);
#pragma unroll
        for (int m = 0; m < 4; m++) {
            ulonglong2 v = wp[m];
            w3r[2 * m] = v.x;
            w3r[2 * m + 1] = v.y;
        }
        if (p3 == 0) b3r = b3[r3];
    }
    if (tid < DD) precs_s[tid] = prec[tid];

    if (wid == 0) {
        float v = fmaf(-0.5f * yv, yv, -0.5f * LOG2PIF);
#pragma unroll
        for (int o = 16; o; o >>= 1) v += __shfl_xor_sync(0xffffffffu, v, o);
        if (lane == 0) s_logpx0 = v;
    }
    __syncthreads();

    for (int step = 0; step < NSTEPS; step++) {
        const float t0 = step * dtf;
        if (step > 0) {
            float acc = yv;
#pragma unroll
            for (int s = 0; s < 6; s++)
                acc = fmaf(dtf * BWc[s], dxsave[(step - 1) * 6 + s][lane], acc);
            yv = acc;
        }
#pragma unroll
        for (int s = 0; s < 6; s++) {
            const int st = step * 6 + s;
            const float ts = t0 + CCc[s] * dtf;

            // ---- P0: stage-x in registers ----
            float sx = yv;
#pragma unroll
            for (int j = 0; j < 5; j++)
                if (j < s)
                    sx = fmaf(dtf * ACc[s][j], dxsave[step * 6 + j][lane], sx);
            if (wid == 0) xsave[st][lane] = sx;
            stxs[wid][lane] = sx;
            __syncwarp();

            // ---- L1: h1 = tanh(W1 x + t u1 + b1) ----
            {
                const ulonglong2* xp = (const ulonglong2*)(stxs[wid] + p1 * 8);
                ull a0 = 0ull, a1 = 0ull;
                ulonglong2 v = xp[0];
                fma2(a0, w1r[0], v.x);
                fma2(a1, w1r[1], v.y);
                v = xp[1];
                fma2(a0, w1r[2], v.x);
                fma2(a1, w1r[3], v.y);
                float zz = sum2(add2(a0, a1));
                zz += __shfl_xor_sync(0xffffffffu, zz, 1);
                zz += __shfl_xor_sync(0xffffffffu, zz, 2);
                if (p1 == 0) {
                    float h = fast_tanh(zz + fmaf(ts, u1r, b1r));
                    float d = fmaf(-h, h, 1.f);
                    if (r1 < 64) {
                        vpool[V_H1LO + r1] = h;
                        vpool[V_D1LO + r1] = d;
                    } else {
                        vpool[V_H1HI + r1 - 64] = h;
                        vpool[V_D1HI + r1 - 64] = d;
                    }
                }
            }
            __syncthreads();  // bar1

            // ---- L2: W2@h1 (tid<256) and G@d1 (tid>=256), half-rows ----
            float gv = 0.f;
            {
                const ulonglong2* vp =
                    (const ulonglong2*)(vpool + (grpB ? V_D1LO : V_H1LO) + half * 68);
                ull a0 = 0ull, a1 = 0ull, a2 = 0ull, a3 = 0ull;
#pragma unroll
                for (int m = 0; m < 16; m++) {
                    ulonglong2 v = vp[m];
                    if (m & 1) {
                        fma2(a2, wr[2 * m], v.x);
                        fma2(a3, wr[2 * m + 1], v.y);
                    } else {
                        fma2(a0, wr[2 * m], v.x);
                        fma2(a1, wr[2 * m + 1], v.y);
                    }
                }
                float acc = sum2(add2(add2(a0, a1), add2(a2, a3)));
                acc += __shfl_xor_sync(0xffffffffu, acc, 1);
                if (!grpB) {
                    if (half == 0) {
                        float h2 = fast_tanh(acc + b2r);
                        h2s[r2] = h2;
                        d2s[r2] = fmaf(-h2, h2, 1.f);
                    }
                } else {
                    gv = acc;
                }
            }
            __syncthreads();  // bar2

            // ---- L3: dx = W3@h2 + b3 (tid<256); trace terms stored (tid>=256) ----
            if (tid < 256) {
                const ulonglong2* hp = (const ulonglong2*)(h2s + p3 * 16);
                ull a0 = 0ull, a1 = 0ull;
#pragma unroll
                for (int m = 0; m < 4; m++) {
                    ulonglong2 v = hp[m];
                    fma2(a0, w3r[2 * m], v.x);
                    fma2(a1, w3r[2 * m + 1], v.y);
                }
                float acc = sum2(add2(a0, a1));
                acc += __shfl_xor_sync(0xffffffffu, acc, 1);
                acc += __shfl_xor_sync(0xffffffffu, acc, 2);
                acc += __shfl_xor_sync(0xffffffffu, acc, 4);
                if (p3 == 0) dxsave[st][r3] = acc + b3r;
            } else {
                if (half == 0) trsave[st][r2] = d2s[r2] * gv;
            }
            __syncthreads();  // bar3
        }
    }

    // ---- tail: all scalar reductions, 3 stages per warp ----
#pragma unroll
    for (int q = 0; q < 3; q++) {
        int st = wid * 3 + q;
        int stp = st / 6;
        int ss = st - 6 * stp;
        float ts = dtf * stp + c_CC[ss] * dtf;
        float x = xsave[st][lane];
        float dx = dxsave[st][lane];
        float r1c = fmaf(-0.5f * x, x, -0.5f * LOG2PIF) * dx;
        float r2c = -precs_s[lane] * x * dx;
        float trc = trsave[st][lane] + trsave[st][lane + 32] +
                    trsave[st][lane + 64] + trsave[st][lane + 96];
#pragma unroll
        for (int o = 16; o; o >>= 1) {
            r1c += __shfl_xor_sync(0xffffffffu, r1c, o);
            r2c += __shfl_xor_sync(0xffffffffu, r2c, o);
            trc += __shfl_xor_sync(0xffffffffu, trc, o);
        }
        if (lane == 0) {
            float omt = 1.0f - ts;
            float dlogp = -trc;
            float dkl = fmaf(-0.5f * omt * omt, r1c,
                             fmaf(-0.5f * omt * (1.0f + ts), r2c, omt * dlogp));
            float w = dtf * c_BW[ss];
            scal[st][0] = w * dlogp;
            scal[st][1] = w * dkl;
        }
    }
    __syncthreads();

    // ---- outputs: z (B,D) | log_px0 + log_det (B,) | kl (B,) ----
    if (wid == 0) {
        float acc = yv;
#pragma unroll
        for (int s = 0; s < 6; s++)
            acc = fmaf(dtf * BWc[s], dxsave[42 + s][lane], acc);
        out[b * DD + lane] = acc;

        float a0 = scal[lane][0] + ((lane < 16) ? scal[lane + 32][0] : 0.f);
        float a1 = scal[lane][1] + ((lane < 16) ? scal[lane + 32][1] : 0.f);
#pragma unroll
        for (int o = 16; o; o >>= 1) {
            a0 += __shfl_xor_sync(0xffffffffu, a0, o);
            a1 += __shfl_xor_sync(0xffffffffu, a1, o);
        }
        if (lane == 0) {
            out[NB * DD + b] = s_logpx0 + a0;
            out[NB * DD + NB + b] = a1;
        }
    }
}

extern "C" void kernel_launch(void* const* d_in, const int* in_sizes, int n_in,
                              void* d_out, int out_size) {
    const float* x0 = (const float*)d_in[0];
    const float* W1 = (const float*)d_in[1];
    const float* u1 = (const float*)d_in[2];
    const float* b1 = (const float*)d_in[3];
    const float* W2 = (const float*)d_in[4];
    const float* b2 = (const float*)d_in[5];
    const float* W3 = (const float*)d_in[6];
    const float* b3 = (const float*)d_in[7];
    const float* prec = (const float*)d_in[8];
    float* out = (float*)d_out;

    precompute_G<<<HH, HH>>>(W1, W2, W3);
    ode_kernel<<<NB, 512>>>(x0, W1, u1, b1, W2, b2, W3, b3, prec, out);
}